// round 12
// baseline (speedup 1.0000x reference)
#include <cuda_runtime.h>
#include <cuda_bf16.h>
#include <cstdint>

// S4 adaptive embedding: bf16 hi/lo split mma.sync + cp.async.bulk task-stream GEMM.
// R12: block tile 128x128 (256 thr, warp 32x64), K-chunk 32 (64B rows, SW64 swizzle),
// 3x32KB stages -> 2 CTAs/SM, pipeline flows across mtile boundaries.

#define NTOK  16384
#define NTOKP 16512
#define DPROJ 1024
#define NB2   16
#define NB3   8

__device__ int g_cnt[4];
__device__ int g_tok[4][NTOK];
__device__ int g_idx[4][NTOK];

__device__ alignas(128) __nv_bfloat16 g_embH[(size_t)NTOKP * 1408];
__device__ alignas(128) __nv_bfloat16 g_embL[(size_t)NTOKP * 1408];
__device__ alignas(128) __nv_bfloat16 g_projH[(size_t)DPROJ * 1408];
__device__ alignas(128) __nv_bfloat16 g_projL[(size_t)DPROJ * 1408];

__constant__ int c_D[4]    = {1024, 256, 64, 16};
__constant__ int c_Dpad[4] = {1024, 256, 64, 32};
__constant__ int c_lgD[4]  = {10, 8, 6, 4};
__constant__ int c_KO[4]   = {0, 1024, 1280, 1344};

struct Params {
    const float* emb[4];
    const float* proj[4];
    float* out;
};

// SW64-style swizzle for 64B rows: toggle bits [4:6) by bits [7:9)
#define SWZ64(off) ((off) ^ (((off) >> 3) & 0x30))

__device__ __forceinline__ uint32_t pack_hi(float x, float y) {
    __nv_bfloat162 t;
    t.x = __float2bfloat16(x);
    t.y = __float2bfloat16(y);
    return *reinterpret_cast<uint32_t*>(&t);
}
__device__ __forceinline__ uint32_t pack_lo(float x, float y) {
    __nv_bfloat16 hx = __float2bfloat16(x), hy = __float2bfloat16(y);
    __nv_bfloat162 t;
    t.x = __float2bfloat16(x - __bfloat162float(hx));
    t.y = __float2bfloat16(y - __bfloat162float(hy));
    return *reinterpret_cast<uint32_t*>(&t);
}

// ---------------- prepasses ----------------
// Layout (both emb and proj): unit (tile128, ck32) = 8KB contiguous,
// row = 64B (32 bf16), SW64 swizzle. 16B group q in [0,4).
__global__ void conv_proj_kernel(Params p) {
    if (blockIdx.x == 0 && blockIdx.y == 0 && threadIdx.x < 4) g_cnt[threadIdx.x] = 0;
    int b = blockIdx.y;
    int D = c_D[b], lgG = c_lgD[b] - 3, G = 1 << lgG, ncb = c_Dpad[b] >> 5;
    const float* src = p.proj[b];
    size_t PB = 2ull * c_KO[b] * DPROJ;
    int total = DPROJ << lgG;
    for (int t = blockIdx.x * 256 + threadIdx.x; t < total; t += gridDim.x * 256) {
        int d = t >> lgG, g8 = t & (G - 1);
        int k0 = g8 << 3;
        const float* s = src + (size_t)d * D + k0;
        float4 va = *(const float4*)s, vb2 = *(const float4*)(s + 4);
        uint4 H = make_uint4(pack_hi(va.x, va.y), pack_hi(va.z, va.w),
                             pack_hi(vb2.x, vb2.y), pack_hi(vb2.z, vb2.w));
        uint4 L = make_uint4(pack_lo(va.x, va.y), pack_lo(va.z, va.w),
                             pack_lo(vb2.x, vb2.y), pack_lo(vb2.z, vb2.w));
        int nt = d >> 7, r = d & 127, ck = k0 >> 5, q = (k0 >> 3) & 3;
        size_t off = PB + (size_t)(nt * ncb + ck) * 8192
                        + SWZ64((uint32_t)(r * 64 + q * 16));
        *(uint4*)((char*)g_projH + off) = H;
        *(uint4*)((char*)g_projL + off) = L;
    }
}

__global__ void bucketize_kernel(const void* ids_raw) {
    const int* w = (const int*)ids_raw;
    int nz = w[2 * threadIdx.x + 1];
    int is64 = (__syncthreads_or(nz) == 0);
    int i = blockIdx.x * 256 + threadIdx.x;
    long long id = is64 ? ((const long long*)ids_raw)[i] : (long long)w[i];
    int b, l;
    if (id < 20000)       { b = 0; l = 0; }
    else if (id < 40000)  { b = 1; l = 20000; }
    else if (id < 200000) { b = 2; l = 40000; }
    else                  { b = 3; l = 200000; }
    int slot = atomicAdd(&g_cnt[b], 1);
    g_tok[b][slot] = i;
    g_idx[b][slot] = (int)(id - l);
}

__global__ void gather_emb_kernel(Params p) {
    int b = blockIdx.y;
    int cnt = g_cnt[b], D = c_D[b], lgG = c_lgD[b] - 3, G = 1 << lgG, ncb = c_Dpad[b] >> 5;
    const float* src = p.emb[b];
    size_t AB = 2ull * c_KO[b] * NTOKP;
    int total = cnt << lgG;
    for (int t = blockIdx.x * 256 + threadIdx.x; t < total; t += gridDim.x * 256) {
        int slot = t >> lgG, g8 = t & (G - 1);
        int k0 = g8 << 3;
        const float* s = src + (size_t)g_idx[b][slot] * D + k0;
        float4 va = *(const float4*)s, vb2 = *(const float4*)(s + 4);
        uint4 H = make_uint4(pack_hi(va.x, va.y), pack_hi(va.z, va.w),
                             pack_hi(vb2.x, vb2.y), pack_hi(vb2.z, vb2.w));
        uint4 L = make_uint4(pack_lo(va.x, va.y), pack_lo(va.z, va.w),
                             pack_lo(vb2.x, vb2.y), pack_lo(vb2.z, vb2.w));
        int mt = slot >> 7, r = slot & 127, ck = k0 >> 5, q = (k0 >> 3) & 3;
        size_t off = AB + (size_t)(mt * ncb + ck) * 8192
                        + SWZ64((uint32_t)(r * 64 + q * 16));
        *(uint4*)((char*)g_embH + off) = H;
        *(uint4*)((char*)g_embL + off) = L;
    }
}

// ---------------- MMA / bulk-copy helpers ----------------
#define LDSM_X4(r, addr) \
    asm volatile("ldmatrix.sync.aligned.m8n8.x4.shared.b16 {%0,%1,%2,%3}, [%4];" \
        : "=r"((r)[0]), "=r"((r)[1]), "=r"((r)[2]), "=r"((r)[3]) : "r"(addr))

#define MMA_BF16(c, a, b0, b1) \
    asm volatile("mma.sync.aligned.m16n8k16.row.col.f32.bf16.bf16.f32 " \
        "{%0,%1,%2,%3}, {%4,%5,%6,%7}, {%8,%9}, {%0,%1,%2,%3};" \
        : "+f"((c)[0]), "+f"((c)[1]), "+f"((c)[2]), "+f"((c)[3]) \
        : "r"((a)[0]), "r"((a)[1]), "r"((a)[2]), "r"((a)[3]), "r"(b0), "r"(b1))

#define CP_BULK(dst, src, bytes, mbar) \
    asm volatile("cp.async.bulk.shared::cta.global.mbarrier::complete_tx::bytes [%0], [%1], %2, [%3];" \
        :: "r"(dst), "l"(src), "r"((uint32_t)(bytes)), "r"(mbar) : "memory")
#define MBAR_INIT(a, c) \
    asm volatile("mbarrier.init.shared.b64 [%0], %1;" :: "r"(a), "r"((uint32_t)(c)) : "memory")
#define MBAR_EXPECT(a, n) \
    asm volatile("mbarrier.arrive.expect_tx.shared.b64 _, [%0], %1;" :: "r"(a), "r"((uint32_t)(n)) : "memory")
#define MBAR_WAIT(a, ph) do { \
    uint32_t _m = (a), _p = (ph), _d; \
    asm volatile("{ .reg .pred p; mbarrier.try_wait.parity.acquire.cta.shared::cta.b64 p, [%1], %2; selp.b32 %0,1,0,p; }" \
        : "=r"(_d) : "r"(_m), "r"(_p) : "memory"); \
    if (!_d) { \
        asm volatile("{ .reg .pred P1; WL_%=: mbarrier.try_wait.parity.acquire.cta.shared::cta.b64 P1, [%0], %1, 0x989680; " \
                     "@P1 bra.uni WD_%=; bra.uni WL_%=; WD_%=: }" :: "r"(_m), "r"(_p) : "memory"); \
    } } while (0)

__device__ __forceinline__ uint32_t smem_u32(const void* p) {
    uint32_t a;
    asm("{ .reg .u64 t; cvta.to.shared.u64 t, %1; cvt.u32.u64 %0, t; }" : "=r"(a) : "l"(p));
    return a;
}

// stage (32KB): AH@0 AL@8K BH@16K BL@24K ; 3 stages ; mbars after
#define STAGEB  32768
#define SM_MBAR 98304
#define GEMM_SMEM 98336

__global__ void __launch_bounds__(256, 2) gemm_kernel(Params p) {
    extern __shared__ __align__(1024) char sm[];
    const int tid  = threadIdx.x;
    const int lane = tid & 31;
    const int wid  = tid >> 5;
    const int wm   = wid & 3;        // 4 strips of 32 rows
    const int wn   = wid >> 2;       // 2 strips of 64 cols

    // decode blockIdx.x -> (bucket, mtile batch) in 128-row tiles
    int cnt0 = g_cnt[0], cnt1 = g_cnt[1], cnt2 = g_cnt[2], cnt3 = g_cnt[3];
    int t0 = (cnt0 + 127) >> 7, t1 = (cnt1 + 127) >> 7;
    int t2 = (cnt2 + 127) >> 7, t3 = (cnt3 + 127) >> 7;
    int x = blockIdx.x, b, n, mts, mte;
    if (x < t0)               { b = 0; n = cnt0; mts = x; mte = x + 1; }
    else if ((x -= t0) < t1)  { b = 1; n = cnt1; mts = x; mte = x + 1; }
    else if ((x -= t1) < NB2) { b = 2; n = cnt2; int bs = (t2 + NB2 - 1) / NB2;
                                mts = x * bs; mte = min(mts + bs, t2); }
    else if ((x -= NB2) < NB3){ b = 3; n = cnt3; int bs = (t3 + NB3 - 1) / NB3;
                                mts = x * bs; mte = min(mts + bs, t3); }
    else return;
    if (mts >= mte) return;

    const int np = blockIdx.y;               // 128-col group
    const int ncb = c_Dpad[b] >> 5;          // {32,8,2,1}
    const int ksteps = (b == 3) ? 1 : 2;
    const int T = (mte - mts) * ncb;

    const char* pAH = (const char*)g_embH + 2ull * c_KO[b] * NTOKP;
    const char* pAL = (const char*)g_embL + 2ull * c_KO[b] * NTOKP;
    const char* pBH = (const char*)g_projH + 2ull * c_KO[b] * DPROJ;
    const char* pBL = (const char*)g_projL + 2ull * c_KO[b] * DPROJ;

    const uint32_t sb = smem_u32(sm);
    const uint32_t mb[3] = {sb + SM_MBAR, sb + SM_MBAR + 8, sb + SM_MBAR + 16};
    if (tid == 0) { MBAR_INIT(mb[0], 1); MBAR_INIT(mb[1], 1); MBAR_INIT(mb[2], 1); }
    __syncthreads();
    int ph[3] = {0, 0, 0};

    auto issue = [&](int t) {
        int mt = mts + t / ncb;
        int ck = t % ncb;
        int s  = t % 3;
        MBAR_EXPECT(mb[s], 32768);
        uint32_t d = sb + s * STAGEB;
        size_t ao = (size_t)(mt * ncb + ck) * 8192;
        size_t bo = (size_t)(np * ncb + ck) * 8192;
        CP_BULK(d,         pAH + ao, 8192, mb[s]);
        CP_BULK(d + 8192,  pAL + ao, 8192, mb[s]);
        CP_BULK(d + 16384, pBH + bo, 8192, mb[s]);
        CP_BULK(d + 24576, pBL + bo, 8192, mb[s]);
    };

    // per-lane fragment address pieces (64B rows)
    const uint32_t a_row = wm * 32 + (lane & 15);
    const uint32_t a_kof2 = ((lane >> 1) & 8) * 2;          // +16B for lanes 16..31
    const int gq = lane >> 3;
    const uint32_t b_rof = ((gq >> 1) & 1) * 8 + (lane & 7);
    const uint32_t b_kof2 = (gq & 1) * 16;                  // +8 cols = 16B

    float acc[2][8][4];
    auto clear_acc = [&]() {
        #pragma unroll
        for (int fm = 0; fm < 2; fm++)
            #pragma unroll
            for (int fn = 0; fn < 8; fn++)
                #pragma unroll
                for (int r = 0; r < 4; r++) acc[fm][fn][r] = 0.f;
    };

    auto do_kstep = [&](int ks, uint32_t base) {
        const uint32_t kb = ks * 32;
        uint32_t af[2][2][4];
        #pragma unroll
        for (int fm = 0; fm < 2; fm++) {
            uint32_t off = SWZ64((a_row + fm * 16) * 64 + kb + a_kof2);
            LDSM_X4(af[0][fm], base + off);          // AH
            LDSM_X4(af[1][fm], base + 8192 + off);   // AL
        }
        #pragma unroll
        for (int half = 0; half < 2; half++) {
            uint32_t bfr[2][2][4];
            #pragma unroll
            for (int j = 0; j < 2; j++) {
                uint32_t r = wn * 64 + (half * 2 + j) * 16 + b_rof;
                uint32_t off = SWZ64(r * 64 + kb + b_kof2);
                LDSM_X4(bfr[0][j], base + 16384 + off);   // BH
                LDSM_X4(bfr[1][j], base + 24576 + off);   // BL
            }
            #pragma unroll
            for (int fm = 0; fm < 2; fm++)
                #pragma unroll
                for (int f = 0; f < 4; f++) {
                    float* c = acc[fm][half * 4 + f];
                    uint32_t b0h = bfr[0][f >> 1][(f & 1) * 2];
                    uint32_t b1h = bfr[0][f >> 1][(f & 1) * 2 + 1];
                    uint32_t b0l = bfr[1][f >> 1][(f & 1) * 2];
                    uint32_t b1l = bfr[1][f >> 1][(f & 1) * 2 + 1];
                    MMA_BF16(c, af[0][fm], b0h, b1h);
                    MMA_BF16(c, af[1][fm], b0h, b1h);
                    MMA_BF16(c, af[0][fm], b0l, b1l);
                }
        }
    };

    auto epilogue = [&](int mt) {
        int m0 = mt << 7;
        #pragma unroll
        for (int fm = 0; fm < 2; fm++) {
            int r0 = wm * 32 + fm * 16 + (lane >> 2);
            int mA = m0 + r0, mB = m0 + r0 + 8;
            int tokA = (mA < n) ? g_tok[b][mA] : -1;
            int tokB = (mB < n) ? g_tok[b][mB] : -1;
            #pragma unroll
            for (int fn = 0; fn < 8; fn++) {
                int c = np * 128 + wn * 64 + fn * 8 + (lane & 3) * 2;
                if (tokA >= 0)
                    *(float2*)(p.out + (size_t)tokA * DPROJ + c) =
                        make_float2(acc[fm][fn][0] * 32.f, acc[fm][fn][1] * 32.f);
                if (tokB >= 0)
                    *(float2*)(p.out + (size_t)tokB * DPROJ + c) =
                        make_float2(acc[fm][fn][2] * 32.f, acc[fm][fn][3] * 32.f);
            }
        }
    };

    if (tid == 0) {
        issue(0);
        if (T > 1) issue(1);
    }

    int mt = mts, ck = 0, s = 0;
    for (int t = 0; t < T; t++) {
        if (t + 2 < T && tid == 0) issue(t + 2);
        MBAR_WAIT(mb[s], ph[s]);
        ph[s] ^= 1;
        if (ck == 0) clear_acc();
        uint32_t base = sb + s * STAGEB;
        do_kstep(0, base);
        if (ksteps == 2) do_kstep(1, base);
        bool last = (ck == ncb - 1);
        if (last) epilogue(mt);
        __syncthreads();
        if (last) { mt++; ck = 0; } else ck++;
        s = (s + 1 == 3) ? 0 : s + 1;
    }
}

extern "C" void kernel_launch(void* const* d_in, const int* in_sizes, int n_in,
                              void* d_out, int out_size) {
    Params p;
    const void* ids = d_in[0];
    p.emb[0]  = (const float*)d_in[1];
    p.proj[0] = (const float*)d_in[2];
    p.emb[1]  = (const float*)d_in[3];
    p.proj[1] = (const float*)d_in[4];
    p.emb[2]  = (const float*)d_in[5];
    p.proj[2] = (const float*)d_in[6];
    p.emb[3]  = (const float*)d_in[7];
    p.proj[3] = (const float*)d_in[8];
    p.out = (float*)d_out;

    cudaFuncSetAttribute(gemm_kernel, cudaFuncAttributeMaxDynamicSharedMemorySize, GEMM_SMEM);

    conv_proj_kernel<<<dim3(512, 4), 256>>>(p);
    bucketize_kernel<<<NTOK / 256, 256>>>(ids);
    gather_emb_kernel<<<dim3(512, 4), 256>>>(p);
    // worst case: 129 mtiles for b0 + 129 for b1 + NB2 + NB3
    gemm_kernel<<<dim3(129 + 129 + NB2 + NB3, DPROJ / 128), 256, GEMM_SMEM>>>(p);
}